// round 1
// baseline (speedup 1.0000x reference)
#include <cuda_runtime.h>
#include <math.h>

// Problem shape (fixed by the dataset)
#define BB 64     // batch
#define TT 128    // tokens (grouped-GEMM group dim)
#define DD 512    // model dim
#define HH 2048   // hidden dim

static constexpr int BM = 64;   // == BB, one tile covers the whole batch dim
static constexpr int BN = 64;
static constexpr int BK = 16;
static constexpr int TM = 4;
static constexpr int TN = 4;
static constexpr int NTHREADS = (BM / TM) * (BN / TN);  // 256

// Intermediate activations h = gelu(x@W1 + b1), layout [B, T, H] (64 MB scratch).
__device__ float g_h[(size_t)BB * TT * HH];

// Generic per-token GEMM:  Out[m, t, n] = act( sum_k A[m, t, k] * W[t, k, n] + bias[t, n] )
//   A   : [B, T, K]  (row m stride = T*K, token offset t*K, k contiguous)
//   W   : [T, K, N]  (k row stride = N, n contiguous)
//   bias: [T, N]
//   Out : [B, T, N]
template <int K, int N, bool DOGELU>
__global__ __launch_bounds__(NTHREADS) void ffn_gemm(
    const float* __restrict__ A,
    const float* __restrict__ W,
    const float* __restrict__ bias,
    float* __restrict__ Out)
{
    const int t  = blockIdx.y;
    const int n0 = blockIdx.x * BN;
    const int tid = threadIdx.x;
    const int tx = tid & 15;   // 0..15 -> n microtile
    const int ty = tid >> 4;   // 0..15 -> m microtile

    __shared__ float As[BK][BM + 4];  // transposed A tile (pad to soften STS conflicts)
    __shared__ float Bs[BK][BN];

    const float* Abase = A + (size_t)t * K;            // + m*(T*K) + k
    const float* Wbase = W + (size_t)t * K * N + n0;   // + k*N + n

    // global-load assignments (one float4 per thread per tile)
    const int am = tid >> 2;          // 0..63  (m row of A tile)
    const int ak = (tid & 3) * 4;     // 0,4,8,12 (k within BK)
    const int bk = tid >> 4;          // 0..15  (k row of B tile)
    const int bn = (tid & 15) * 4;    // 0..60  (n within BN)

    float acc[TM][TN];
#pragma unroll
    for (int i = 0; i < TM; i++)
#pragma unroll
        for (int j = 0; j < TN; j++) acc[i][j] = 0.0f;

    for (int k0 = 0; k0 < K; k0 += BK) {
        float4 av = *reinterpret_cast<const float4*>(
            Abase + (size_t)am * (TT * (size_t)K) + (size_t)(k0 + ak));
        float4 bv = *reinterpret_cast<const float4*>(
            Wbase + (size_t)(k0 + bk) * N + bn);

        As[ak + 0][am] = av.x;
        As[ak + 1][am] = av.y;
        As[ak + 2][am] = av.z;
        As[ak + 3][am] = av.w;
        *reinterpret_cast<float4*>(&Bs[bk][bn]) = bv;
        __syncthreads();

#pragma unroll
        for (int kk = 0; kk < BK; kk++) {
            float a[TM], b[TN];
#pragma unroll
            for (int i = 0; i < TM; i++) a[i] = As[kk][ty * TM + i];
#pragma unroll
            for (int j = 0; j < TN; j++) b[j] = Bs[kk][tx * TN + j];
#pragma unroll
            for (int i = 0; i < TM; i++)
#pragma unroll
                for (int j = 0; j < TN; j++)
                    acc[i][j] = fmaf(a[i], b[j], acc[i][j]);
        }
        __syncthreads();
    }

    // epilogue: bias (+ exact-erf GELU) and store
#pragma unroll
    for (int i = 0; i < TM; i++) {
        const int m = ty * TM + i;                 // batch index (BM == BB)
#pragma unroll
        for (int j = 0; j < TN; j++) {
            const int n = n0 + tx * TN + j;
            float v = acc[i][j] + bias[(size_t)t * N + n];
            if (DOGELU) {
                v = 0.5f * v * (1.0f + erff(v * 0.70710678118654752440f));
            }
            Out[(size_t)m * TT * N + (size_t)t * N + n] = v;
        }
    }
}

extern "C" void kernel_launch(void* const* d_in, const int* in_sizes, int n_in,
                              void* d_out, int out_size)
{
    (void)in_sizes; (void)n_in; (void)out_size;
    const float* x  = (const float*)d_in[0];  // [B, T, D]
    const float* W1 = (const float*)d_in[1];  // [T, D, H]
    const float* b1 = (const float*)d_in[2];  // [T, H]
    const float* W2 = (const float*)d_in[3];  // [T, H, D]
    const float* b2 = (const float*)d_in[4];  // [T, D]
    float* out = (float*)d_out;               // [B, T, D]

    float* h = nullptr;
    cudaGetSymbolAddress((void**)&h, g_h);

    // GEMM1 + GELU:  h = gelu(x @ W1 + b1)   [M=64, N=2048, K=512] x 128 tokens
    ffn_gemm<DD, HH, true><<<dim3(HH / BN, TT), NTHREADS>>>(x, W1, b1, h);
    // GEMM2:        out = h @ W2 + b2        [M=64, N=512, K=2048] x 128 tokens
    ffn_gemm<HH, DD, false><<<dim3(DD / BN, TT), NTHREADS>>>(h, W2, b2, out);
}

// round 3
// speedup vs baseline: 1.7068x; 1.7068x over previous
#include <cuda_runtime.h>
#include <cuda_bf16.h>
#include <cstdint>
#include <math.h>

// Problem shape
#define BB 64
#define TT 128
#define DD 512
#define HH 2048

// Intermediate h = gelu(x@W1+b1), layout [t][m][hidx] (fp32, 64MB)
__device__ float g_h[(size_t)TT * BB * HH];

static constexpr int SA = 40;   // padded SMEM row stride in bf16 elems (80 B)
static constexpr int NT = 256;  // threads per CTA (8 warps)

// ───────────── helpers ─────────────
__device__ __forceinline__ uint32_t smem_u32(const void* p) {
    uint32_t a;
    asm("{ .reg .u64 t; cvta.to.shared.u64 t, %1; cvt.u32.u64 %0, t; }" : "=r"(a) : "l"(p));
    return a;
}
__device__ __forceinline__ void ldsm_x4(uint32_t* r, uint32_t addr) {
    asm volatile("ldmatrix.sync.aligned.m8n8.x4.shared.b16 {%0,%1,%2,%3}, [%4];"
                 : "=r"(r[0]), "=r"(r[1]), "=r"(r[2]), "=r"(r[3]) : "r"(addr));
}
__device__ __forceinline__ void mma16816(float* c, const uint32_t* a, uint32_t b0, uint32_t b1) {
    asm volatile("mma.sync.aligned.m16n8k16.row.col.f32.bf16.bf16.f32 "
                 "{%0,%1,%2,%3}, {%4,%5,%6,%7}, {%8,%9}, {%0,%1,%2,%3};"
                 : "+f"(c[0]), "+f"(c[1]), "+f"(c[2]), "+f"(c[3])
                 : "r"(a[0]), "r"(a[1]), "r"(a[2]), "r"(a[3]), "r"(b0), "r"(b1));
}
// split two fp32 into packed bf16 hi-pair and lo-pair (x = low half = smaller k)
__device__ __forceinline__ void split2(float x, float y, uint32_t& hi, uint32_t& lo) {
    __nv_bfloat16 hx = __float2bfloat16(x);
    __nv_bfloat16 hy = __float2bfloat16(y);
    __nv_bfloat16 lx = __float2bfloat16(x - __bfloat162float(hx));
    __nv_bfloat16 ly = __float2bfloat16(y - __bfloat162float(hy));
    hi = ((uint32_t)(*reinterpret_cast<uint16_t*>(&hy)) << 16) | *reinterpret_cast<uint16_t*>(&hx);
    lo = ((uint32_t)(*reinterpret_cast<uint16_t*>(&ly)) << 16) | *reinterpret_cast<uint16_t*>(&lx);
}

// ───────────── FFN GEMM via mma.sync (split-fp32, 3 bf16 passes) ─────────────
// Per CTA: token t, output block n0..n0+63.
//   Out[t*OTS + m*OMS + n0+n] = act( sum_k Act[m,k] * W[t][k, n0+n] + bias[t, n0+n] )
// Act element (m,k) at Act + t*ATS + m*AMS + k (k contiguous).
template <int K, int NFULL, int ATS, int AMS, int OTS, int OMS, bool DOGELU>
__global__ void __launch_bounds__(NT)
ffn_mma(const float* __restrict__ W, const float* __restrict__ Act,
        const float* __restrict__ bias, float* __restrict__ Out)
{
    __shared__ uint32_t sAhi[64 * SA / 2];  // act tile   [64 m][32 k] bf16 (padded)
    __shared__ uint32_t sAlo[64 * SA / 2];
    __shared__ uint32_t sWhi[64 * SA / 2];  // weight tile [64 n][32 k] bf16 (padded)
    __shared__ uint32_t sWlo[64 * SA / 2];

    const int t   = blockIdx.y;
    const int n0  = blockIdx.x * 64;
    const int tid = threadIdx.x;
    const int wid = tid >> 5;
    const int lane = tid & 31;

    const float* At = Act + (size_t)t * ATS;
    const float* Wt = W + (size_t)t * K * NFULL + n0;

    // warp tile: m16 x n32
    const int mw = (wid >> 1) * 16;
    const int nw = (wid & 1) * 32;

    // ldmatrix lane addresses (bytes)
    const uint32_t aOff = (uint32_t)(((mw + (lane & 15)) * SA + ((lane >> 4) * 8)) * 2);
    const uint32_t bOff = (uint32_t)(((nw + ((lane >> 4) << 3) + (lane & 7)) * SA +
                                      (((lane >> 3) & 1) * 8)) * 2);
    const uint32_t aHi = smem_u32(sAhi) + aOff;
    const uint32_t aLo = smem_u32(sAlo) + aOff;
    const uint32_t bHi = smem_u32(sWhi) + bOff;
    const uint32_t bLo = smem_u32(sWlo) + bOff;

    // W-tile load assignment: 64 threads per k-group of 8 rows
    const int wn = tid & 63;
    const int wkg = tid >> 6;  // 0..3

    float acc[16];  // [np*2 + atom][4]
#pragma unroll
    for (int i = 0; i < 16; i++) acc[i] = 0.0f;

    constexpr int NCHUNK = K / 32;
    for (int c = 0; c < NCHUNK; c++) {
        // ---- stage act tile: 64 m x 32 k fp32 -> bf16 hi/lo ----
#pragma unroll
        for (int it = 0; it < 2; it++) {
            int idx = it * NT + tid;         // 0..511
            int m = idx >> 3;
            int k4 = (idx & 7) * 4;
            float4 v = *reinterpret_cast<const float4*>(At + (size_t)m * AMS + c * 32 + k4);
            uint32_t h0, l0, h1, l1;
            split2(v.x, v.y, h0, l0);
            split2(v.z, v.w, h1, l1);
            int si = m * (SA / 2) + (k4 >> 1);
            *reinterpret_cast<uint2*>(&sAhi[si]) = make_uint2(h0, h1);
            *reinterpret_cast<uint2*>(&sAlo[si]) = make_uint2(l0, l1);
        }
        // ---- stage weight tile: 32 k x 64 n fp32 -> transposed [n][k] bf16 hi/lo ----
        {
            const float* p = Wt + (size_t)(c * 32 + wkg * 8) * NFULL + wn;
            float v[8];
#pragma unroll
            for (int r = 0; r < 8; r++) v[r] = p[(size_t)r * NFULL];
            uint32_t h[4], l[4];
#pragma unroll
            for (int r = 0; r < 4; r++) split2(v[2 * r], v[2 * r + 1], h[r], l[r]);
            int si = wn * (SA / 2) + wkg * 4;
            *reinterpret_cast<uint4*>(&sWhi[si]) = make_uint4(h[0], h[1], h[2], h[3]);
            *reinterpret_cast<uint4*>(&sWlo[si]) = make_uint4(l[0], l[1], l[2], l[3]);
        }
        __syncthreads();

        // ---- MMA: 2 ksteps x 2 npairs x (hi*hi + hi*lo + lo*hi) ----
#pragma unroll
        for (int ks = 0; ks < 2; ks++) {
            uint32_t ah[4], al[4];
            ldsm_x4(ah, aHi + ks * 32);
            ldsm_x4(al, aLo + ks * 32);
#pragma unroll
            for (int np = 0; np < 2; np++) {
                uint32_t bh[4], bl[4];
                ldsm_x4(bh, bHi + np * (16 * SA * 2) + ks * 32);
                ldsm_x4(bl, bLo + np * (16 * SA * 2) + ks * 32);
                float* c0 = acc + (np * 2 + 0) * 4;
                float* c1 = acc + (np * 2 + 1) * 4;
                mma16816(c0, ah, bh[0], bh[1]);
                mma16816(c1, ah, bh[2], bh[3]);
                mma16816(c0, ah, bl[0], bl[1]);
                mma16816(c1, ah, bl[2], bl[3]);
                mma16816(c0, al, bh[0], bh[1]);
                mma16816(c1, al, bh[2], bh[3]);
            }
        }
        __syncthreads();
    }

    // ---- epilogue: bias (+ exact-erf GELU), direct register -> global ----
    const int gid = lane >> 2;
    const int tig = lane & 3;
    const float* bt = bias + (size_t)t * NFULL + n0;
    float* outT = Out + (size_t)t * OTS + n0;
#pragma unroll
    for (int a4 = 0; a4 < 4; a4++) {
        int n = nw + (a4 >> 1) * 16 + (a4 & 1) * 8 + tig * 2;
        float bv0 = bt[n], bv1 = bt[n + 1];
        int m0 = mw + gid, m1 = mw + gid + 8;
        float v00 = acc[a4 * 4 + 0] + bv0;
        float v01 = acc[a4 * 4 + 1] + bv1;
        float v10 = acc[a4 * 4 + 2] + bv0;
        float v11 = acc[a4 * 4 + 3] + bv1;
        if (DOGELU) {
            const float r2 = 0.70710678118654752440f;
            v00 = 0.5f * v00 * (1.0f + erff(v00 * r2));
            v01 = 0.5f * v01 * (1.0f + erff(v01 * r2));
            v10 = 0.5f * v10 * (1.0f + erff(v10 * r2));
            v11 = 0.5f * v11 * (1.0f + erff(v11 * r2));
        }
        *reinterpret_cast<float2*>(outT + (size_t)m0 * OMS + n) = make_float2(v00, v01);
        *reinterpret_cast<float2*>(outT + (size_t)m1 * OMS + n) = make_float2(v10, v11);
    }
}

// ───────────── host launcher ─────────────
extern "C" void kernel_launch(void* const* d_in, const int* in_sizes, int n_in,
                              void* d_out, int out_size)
{
    (void)in_sizes; (void)n_in; (void)out_size;
    const float* x  = (const float*)d_in[0];  // [B, T, D]
    const float* W1 = (const float*)d_in[1];  // [T, D, H]
    const float* b1 = (const float*)d_in[2];  // [T, H]
    const float* W2 = (const float*)d_in[3];  // [T, H, D]
    const float* b2 = (const float*)d_in[4];  // [T, D]
    float* out = (float*)d_out;               // [B, T, D]

    float* h = nullptr;
    cudaGetSymbolAddress((void**)&h, g_h);

    // GEMM1 + GELU:  h[t][m][n] = gelu( sum_d x[m,t,d] * W1[t][d,n] + b1[t,n] )
    //   Act = x: ATS=DD, AMS=TT*DD;  Out = h: OTS=BB*HH, OMS=HH
    ffn_mma<DD, HH, DD, TT * DD, BB * HH, HH, true>
        <<<dim3(HH / 64, TT), NT>>>(W1, x, b1, h);

    // GEMM2: out[m][t][n] = sum_h h[t][m][h] * W2[t][h,n] + b2[t,n]
    //   Act = h: ATS=BB*HH, AMS=HH;  Out: OTS=DD, OMS=TT*DD
    ffn_mma<HH, DD, BB * HH, HH, DD, TT * DD, false>
        <<<dim3(DD / 64, TT), NT>>>(W2, h, b2, out);
}

// round 4
// speedup vs baseline: 2.4914x; 1.4597x over previous
#include <cuda_runtime.h>
#include <cuda_bf16.h>
#include <cstdint>
#include <math.h>

// Problem shape
#define BB 64
#define TT 128
#define DD 512
#define HH 2048

// Intermediate h = gelu(x@W1+b1), layout [t][m][hidx] (fp32, 64MB)
__device__ float g_h[(size_t)TT * BB * HH];

static constexpr int SA = 40;   // padded SMEM row stride in bf16 (80 B, ldsm conflict-free)
static constexpr int NT = 256;  // 8 warps

// dynamic SMEM stage layout (bytes)
static constexpr int A_HI = 0;            // act  [64 m][32 k] bf16 hi  (5120)
static constexpr int A_LO = 5120;         // act lo                      (5120)
static constexpr int W_HI = 10240;        // wgt  [128 n][32 k] bf16 hi (10240)
static constexpr int W_LO = 20480;        // wgt lo                     (10240)
static constexpr int STAGE = 30720;
static constexpr int SMEM_BYTES = 2 * STAGE;  // 61440

// ───────────── helpers ─────────────
__device__ __forceinline__ uint32_t smem_u32(const void* p) {
    uint32_t a;
    asm("{ .reg .u64 t; cvta.to.shared.u64 t, %1; cvt.u32.u64 %0, t; }" : "=r"(a) : "l"(p));
    return a;
}
__device__ __forceinline__ void ldsm_x4(uint32_t* r, uint32_t addr) {
    asm volatile("ldmatrix.sync.aligned.m8n8.x4.shared.b16 {%0,%1,%2,%3}, [%4];"
                 : "=r"(r[0]), "=r"(r[1]), "=r"(r[2]), "=r"(r[3]) : "r"(addr));
}
__device__ __forceinline__ void mma16816(float* c, const uint32_t* a, uint32_t b0, uint32_t b1) {
    asm volatile("mma.sync.aligned.m16n8k16.row.col.f32.bf16.bf16.f32 "
                 "{%0,%1,%2,%3}, {%4,%5,%6,%7}, {%8,%9}, {%0,%1,%2,%3};"
                 : "+f"(c[0]), "+f"(c[1]), "+f"(c[2]), "+f"(c[3])
                 : "r"(a[0]), "r"(a[1]), "r"(a[2]), "r"(a[3]), "r"(b0), "r"(b1));
}
// split two fp32 into packed bf16 hi-pair and lo-pair (x = low half = smaller k)
__device__ __forceinline__ void split2(float x, float y, uint32_t& hi, uint32_t& lo) {
    __nv_bfloat16 hx = __float2bfloat16(x);
    __nv_bfloat16 hy = __float2bfloat16(y);
    __nv_bfloat16 lx = __float2bfloat16(x - __bfloat162float(hx));
    __nv_bfloat16 ly = __float2bfloat16(y - __bfloat162float(hy));
    hi = ((uint32_t)(*reinterpret_cast<uint16_t*>(&hy)) << 16) | *reinterpret_cast<uint16_t*>(&hx);
    lo = ((uint32_t)(*reinterpret_cast<uint16_t*>(&ly)) << 16) | *reinterpret_cast<uint16_t*>(&lx);
}

// ───────────── FFN GEMM via mma.sync (split-fp32, 3 bf16 passes, pipelined) ─────────────
// Per CTA: token t, output block n0..n0+127 (128 weight columns), full batch m=0..63.
//   Out[t*OTS + m*OMS + n0+n] = act( sum_k Act[m,k] * W[t][k, n0+n] + bias[t, n0+n] )
template <int K, int NFULL, int ATS, int AMS, int OTS, int OMS, bool DOGELU>
__global__ void __launch_bounds__(NT)
ffn_mma(const float* __restrict__ W, const float* __restrict__ Act,
        const float* __restrict__ bias, float* __restrict__ Out)
{
    extern __shared__ char smem[];
    const int t    = blockIdx.y;
    const int n0   = blockIdx.x * 128;
    const int tid  = threadIdx.x;
    const int wid  = tid >> 5;
    const int lane = tid & 31;
    const uint32_t sbase = smem_u32(smem);

    const float* At = Act + (size_t)t * ATS;
    const float* Wt = W + (size_t)t * K * NFULL + n0;

    // warp tile: m32 x n32
    const int mw = (wid >> 2) * 32;
    const int nwarp = (wid & 3) * 32;

    // ldmatrix per-lane byte offsets (relative to tile region + warp row base)
    const uint32_t aLaneOff = (uint32_t)(((lane & 15) * SA + (lane >> 4) * 8) * 2);
    const uint32_t bLaneOff = (uint32_t)(((((lane >> 4) << 3) + (lane & 7)) * SA +
                                          (((lane >> 3) & 1) * 8)) * 2);

    // staging assignments
    const int am0 = tid >> 3;               // act: idx 0..255 -> m, k4
    const int ak0 = (tid & 7) * 4;
    const int am1 = (NT + tid) >> 3;        // idx 256..511
    const int ak1 = ((NT + tid) & 7) * 4;
    const int wn  = tid & 127;              // weights: column n, k-group of 16 rows
    const int wkg = tid >> 7;               // 0/1

    float acc[32];                          // [mf][np][atom][4]
#pragma unroll
    for (int i = 0; i < 32; i++) acc[i] = 0.0f;

    float4 pa0, pa1;
    float pw[16];

    auto LOADS = [&](int c) {
        pa0 = *reinterpret_cast<const float4*>(At + (size_t)am0 * AMS + c * 32 + ak0);
        pa1 = *reinterpret_cast<const float4*>(At + (size_t)am1 * AMS + c * 32 + ak1);
        const float* p = Wt + (size_t)(c * 32 + wkg * 16) * NFULL + wn;
#pragma unroll
        for (int r = 0; r < 16; r++) pw[r] = p[(size_t)r * NFULL];
    };

    auto STORE = [&](int s) {
        char* st = smem + s * STAGE;
        {
            uint32_t h0, l0, h1, l1;
            split2(pa0.x, pa0.y, h0, l0); split2(pa0.z, pa0.w, h1, l1);
            int bo = am0 * (SA * 2) + ak0 * 2;
            *reinterpret_cast<uint2*>(st + A_HI + bo) = make_uint2(h0, h1);
            *reinterpret_cast<uint2*>(st + A_LO + bo) = make_uint2(l0, l1);
            split2(pa1.x, pa1.y, h0, l0); split2(pa1.z, pa1.w, h1, l1);
            bo = am1 * (SA * 2) + ak1 * 2;
            *reinterpret_cast<uint2*>(st + A_HI + bo) = make_uint2(h0, h1);
            *reinterpret_cast<uint2*>(st + A_LO + bo) = make_uint2(l0, l1);
        }
        {
            uint32_t h[8], l[8];
#pragma unroll
            for (int r = 0; r < 8; r++) split2(pw[2 * r], pw[2 * r + 1], h[r], l[r]);
            int bo = wn * (SA * 2) + wkg * 32;
            *reinterpret_cast<uint4*>(st + W_HI + bo)      = make_uint4(h[0], h[1], h[2], h[3]);
            *reinterpret_cast<uint4*>(st + W_HI + bo + 16) = make_uint4(h[4], h[5], h[6], h[7]);
            *reinterpret_cast<uint4*>(st + W_LO + bo)      = make_uint4(l[0], l[1], l[2], l[3]);
            *reinterpret_cast<uint4*>(st + W_LO + bo + 16) = make_uint4(l[4], l[5], l[6], l[7]);
        }
    };

    auto MMA = [&](int s) {
        const uint32_t ab = sbase + s * STAGE;
        const uint32_t aHi = ab + A_HI + mw * (SA * 2) + aLaneOff;
        const uint32_t aLo = ab + A_LO + mw * (SA * 2) + aLaneOff;
        const uint32_t bHi = ab + W_HI + nwarp * (SA * 2) + bLaneOff;
        const uint32_t bLo = ab + W_LO + nwarp * (SA * 2) + bLaneOff;
#pragma unroll
        for (int ks = 0; ks < 2; ks++) {
            uint32_t ah[2][4], al[2][4];
#pragma unroll
            for (int mf = 0; mf < 2; mf++) {
                ldsm_x4(ah[mf], aHi + mf * (16 * SA * 2) + ks * 32);
                ldsm_x4(al[mf], aLo + mf * (16 * SA * 2) + ks * 32);
            }
#pragma unroll
            for (int np = 0; np < 2; np++) {
                uint32_t bh[4], bl[4];
                ldsm_x4(bh, bHi + np * (16 * SA * 2) + ks * 32);
                ldsm_x4(bl, bLo + np * (16 * SA * 2) + ks * 32);
#pragma unroll
                for (int mf = 0; mf < 2; mf++) {
                    float* c0 = acc + ((mf * 2 + np) * 2 + 0) * 4;
                    float* c1 = acc + ((mf * 2 + np) * 2 + 1) * 4;
                    mma16816(c0, ah[mf], bh[0], bh[1]);
                    mma16816(c1, ah[mf], bh[2], bh[3]);
                    mma16816(c0, ah[mf], bl[0], bl[1]);
                    mma16816(c1, ah[mf], bl[2], bl[3]);
                    mma16816(c0, al[mf], bh[0], bh[1]);
                    mma16816(c1, al[mf], bh[2], bh[3]);
                }
            }
        }
    };

    constexpr int NCHUNK = K / 32;
    LOADS(0);
    STORE(0);
    __syncthreads();
#pragma unroll 1
    for (int c = 0; c < NCHUNK; c++) {
        const bool more = (c + 1 < NCHUNK);
        if (more) LOADS(c + 1);   // LDG latency hidden behind the MMAs below
        MMA(c & 1);
        if (more) STORE((c + 1) & 1);
        __syncthreads();
    }

    // ---- epilogue: bias (+ exact-erf GELU), registers -> global ----
    const int gid = lane >> 2;
    const int tig = lane & 3;
    const float* bt = bias + (size_t)t * NFULL + n0;
    float* outT = Out + (size_t)t * OTS + n0;
#pragma unroll
    for (int mf = 0; mf < 2; mf++) {
#pragma unroll
        for (int np = 0; np < 2; np++) {
#pragma unroll
            for (int atom = 0; atom < 2; atom++) {
                const float* a = acc + ((mf * 2 + np) * 2 + atom) * 4;
                int n = nwarp + np * 16 + atom * 8 + tig * 2;
                float bv0 = bt[n], bv1 = bt[n + 1];
                int m0 = mw + mf * 16 + gid;
                float v00 = a[0] + bv0, v01 = a[1] + bv1;
                float v10 = a[2] + bv0, v11 = a[3] + bv1;
                if (DOGELU) {
                    const float r2 = 0.70710678118654752440f;
                    v00 = 0.5f * v00 * (1.0f + erff(v00 * r2));
                    v01 = 0.5f * v01 * (1.0f + erff(v01 * r2));
                    v10 = 0.5f * v10 * (1.0f + erff(v10 * r2));
                    v11 = 0.5f * v11 * (1.0f + erff(v11 * r2));
                }
                *reinterpret_cast<float2*>(outT + (size_t)m0 * OMS + n) = make_float2(v00, v01);
                *reinterpret_cast<float2*>(outT + (size_t)(m0 + 8) * OMS + n) = make_float2(v10, v11);
            }
        }
    }
}

// ───────────── host launcher ─────────────
extern "C" void kernel_launch(void* const* d_in, const int* in_sizes, int n_in,
                              void* d_out, int out_size)
{
    (void)in_sizes; (void)n_in; (void)out_size;
    const float* x  = (const float*)d_in[0];  // [B, T, D]
    const float* W1 = (const float*)d_in[1];  // [T, D, H]
    const float* b1 = (const float*)d_in[2];  // [T, H]
    const float* W2 = (const float*)d_in[3];  // [T, H, D]
    const float* b2 = (const float*)d_in[4];  // [T, D]
    float* out = (float*)d_out;               // [B, T, D]

    float* h = nullptr;
    cudaGetSymbolAddress((void**)&h, g_h);

    // GEMM1 + GELU:  h[t][m][n] = gelu( sum_d x[m,t,d] * W1[t][d,n] + b1[t,n] )
    auto k1 = ffn_mma<DD, HH, DD, TT * DD, BB * HH, HH, true>;
    cudaFuncSetAttribute(k1, cudaFuncAttributeMaxDynamicSharedMemorySize, SMEM_BYTES);
    k1<<<dim3(HH / 128, TT), NT, SMEM_BYTES>>>(W1, x, b1, h);

    // GEMM2: out[m][t][n] = sum_h h[t][m][h] * W2[t][h,n] + b2[t,n]
    auto k2 = ffn_mma<HH, DD, BB * HH, HH, DD, TT * DD, false>;
    cudaFuncSetAttribute(k2, cudaFuncAttributeMaxDynamicSharedMemorySize, SMEM_BYTES);
    k2<<<dim3(DD / 128, TT), NT, SMEM_BYTES>>>(W2, h, b2, out);
}